// round 7
// baseline (speedup 1.0000x reference)
#include <cuda_runtime.h>
#include <cuda_bf16.h>
#include <math.h>

// ---------------------------------------------------------------------------
// SMPL LBS point deformer — 2-kernel version.
// Inputs (metadata order):
//  0 points      (3, N)        float32
//  1 weights     (24, N)       float32
//  2 beta        (10,)         float32
//  3 theta       (24, 3)       float32
//  4 da_theta    (24, 3)       float32
//  5 shapedirs   (NV, 3, 10)   float32
//  6 v_template  (NV, 3)       float32
//  7 J_regressor (24, NV)      float32
// Output: (1, 3, N) float32
// ---------------------------------------------------------------------------

#define NJ 24

__constant__ int c_par[NJ] = {-1,0,0,0,1,2,3,4,5,6,7,8,9,9,9,12,13,14,16,17,18,19,20,21};

__device__ float g_J[2][NJ * 3];   // [0]=pose (shaped), [1]=da (template)
__device__ float g_A[NJ * 12];     // row-major 3x4 per joint
__device__ int   g_ctr;            // zero-init; finisher resets to 0 each run

// ---------------------------------------------------------------------------
// Kernel 1: fused prep. 24 blocks (one per joint) compute joint locations
// (with v_shaped formed inline: J = Jreg@(v_template + shapedirs@beta)).
// The last block to finish then runs Rodrigues + kinematic chain + pack +
// A = pose * rigid_inverse(da).
// ---------------------------------------------------------------------------
__global__ void __launch_bounds__(256) k_prep(
    const float* __restrict__ Jreg,
    const float* __restrict__ v_template,
    const float* __restrict__ shapedirs,
    const float* __restrict__ beta,
    const float* __restrict__ theta,
    const float* __restrict__ da_theta,
    int nv) {
    int j = blockIdx.x;
    int tid = threadIdx.x;

    float b[10];
#pragma unroll
    for (int k = 0; k < 10; k++) b[k] = __ldg(&beta[k]);

    // --- phase 1: joint j location (pose & da) ---
    float p0 = 0.f, p1 = 0.f, p2 = 0.f;   // pose (shaped)
    float d0 = 0.f, d1 = 0.f, d2 = 0.f;   // da (template)
    const float* r = Jreg + (size_t)j * nv;
    for (int v = tid; v < nv; v += 256) {
        float w = r[v];
        float t0 = v_template[v * 3 + 0];
        float t1 = v_template[v * 3 + 1];
        float t2 = v_template[v * 3 + 2];
        const float* sd = shapedirs + (size_t)v * 30;
        float s0 = t0, s1 = t1, s2 = t2;
#pragma unroll
        for (int k = 0; k < 10; k++) {
            s0 += sd[k]      * b[k];
            s1 += sd[10 + k] * b[k];
            s2 += sd[20 + k] * b[k];
        }
        d0 += w * t0; d1 += w * t1; d2 += w * t2;
        p0 += w * s0; p1 += w * s1; p2 += w * s2;
    }
#pragma unroll
    for (int off = 16; off > 0; off >>= 1) {
        p0 += __shfl_down_sync(0xffffffffu, p0, off);
        p1 += __shfl_down_sync(0xffffffffu, p1, off);
        p2 += __shfl_down_sync(0xffffffffu, p2, off);
        d0 += __shfl_down_sync(0xffffffffu, d0, off);
        d1 += __shfl_down_sync(0xffffffffu, d1, off);
        d2 += __shfl_down_sync(0xffffffffu, d2, off);
    }
    __shared__ float red[8][6];
    int lane = tid & 31, warp = tid >> 5;
    if (lane == 0) {
        red[warp][0] = p0; red[warp][1] = p1; red[warp][2] = p2;
        red[warp][3] = d0; red[warp][4] = d1; red[warp][5] = d2;
    }
    __syncthreads();
    __shared__ int s_last;
    if (tid == 0) {
        float s[6] = {0, 0, 0, 0, 0, 0};
        for (int w = 0; w < 8; w++)
            for (int k = 0; k < 6; k++) s[k] += red[w][k];
        g_J[0][j * 3 + 0] = s[0]; g_J[0][j * 3 + 1] = s[1]; g_J[0][j * 3 + 2] = s[2];
        g_J[1][j * 3 + 0] = s[3]; g_J[1][j * 3 + 1] = s[4]; g_J[1][j * 3 + 2] = s[5];
        __threadfence();
        s_last = (atomicAdd(&g_ctr, 1) == NJ - 1);
    }
    __syncthreads();
    if (!s_last) return;

    // --- phase 2: last block does the transforms ---
    __shared__ float sJ[2][NJ * 3];
    if (tid < 2 * NJ * 3) {
        int s = tid / (NJ * 3), i = tid % (NJ * 3);
        sJ[s][i] = __ldcg(&g_J[s][i]);      // bypass L1: other blocks wrote these
    }
    __syncthreads();

    __shared__ float L[2][NJ][12];
    __shared__ float G[2][NJ][12];

    if (tid < 48) {
        int s = tid / NJ;          // 0 = pose, 1 = da
        int jj = tid % NJ;
        const float* th = (s == 0 ? theta : da_theta) + jj * 3;
        float rx = th[0], ry = th[1], rz = th[2];
        float nrm = sqrtf(rx * rx + ry * ry + rz * rz) + 1e-8f;
        float x = rx / nrm, y = ry / nrm, z = rz / nrm;
        float c = cosf(nrm), sn = sinf(nrm), ic = 1.0f - c;
        float* Lj = L[s][jj];
        Lj[0] = c + ic * x * x;      Lj[1] = ic * x * y - sn * z;  Lj[2] = ic * x * z + sn * y;
        Lj[3] = ic * x * y + sn * z; Lj[4] = c + ic * y * y;       Lj[5] = ic * y * z - sn * x;
        Lj[6] = ic * x * z - sn * y; Lj[7] = ic * y * z + sn * x;  Lj[8] = c + ic * z * z;
        const float* J = sJ[s];
        int p = c_par[jj];
        if (p < 0) {
            Lj[9] = J[0]; Lj[10] = J[1]; Lj[11] = J[2];
        } else {
            Lj[9]  = J[jj * 3 + 0] - J[p * 3 + 0];
            Lj[10] = J[jj * 3 + 1] - J[p * 3 + 1];
            Lj[11] = J[jj * 3 + 2] - J[p * 3 + 2];
        }
    }
    __syncthreads();

    if (tid < 2) {
        int s = tid;
        for (int k = 0; k < 12; k++) G[s][0][k] = L[s][0][k];
        for (int jj = 1; jj < NJ; jj++) {
            int p = c_par[jj];
            const float* Gp = G[s][p];
            const float* Lj = L[s][jj];
            float* Gj = G[s][jj];
            for (int rr = 0; rr < 3; rr++) {
                for (int cc = 0; cc < 3; cc++)
                    Gj[rr * 3 + cc] = Gp[rr * 3 + 0] * Lj[0 * 3 + cc] +
                                      Gp[rr * 3 + 1] * Lj[1 * 3 + cc] +
                                      Gp[rr * 3 + 2] * Lj[2 * 3 + cc];
                Gj[9 + rr] = Gp[rr * 3 + 0] * Lj[9] + Gp[rr * 3 + 1] * Lj[10] +
                             Gp[rr * 3 + 2] * Lj[11] + Gp[9 + rr];
            }
        }
        // pack: t -= R @ J_rest
        for (int jj = 0; jj < NJ; jj++) {
            const float* J = &sJ[s][jj * 3];
            float* Gj = G[s][jj];
            for (int rr = 0; rr < 3; rr++)
                Gj[9 + rr] -= Gj[rr * 3 + 0] * J[0] + Gj[rr * 3 + 1] * J[1] +
                              Gj[rr * 3 + 2] * J[2];
        }
    }
    __syncthreads();

    if (tid < NJ) {
        int jj = tid;
        const float* P = G[0][jj];   // pose
        const float* D = G[1][jj];   // da (rigid: R orthogonal)
        float AR[9];
        for (int rr = 0; rr < 3; rr++)
            for (int cc = 0; cc < 3; cc++)
                AR[rr * 3 + cc] = P[rr * 3 + 0] * D[cc * 3 + 0] +
                                  P[rr * 3 + 1] * D[cc * 3 + 1] +
                                  P[rr * 3 + 2] * D[cc * 3 + 2];
        float ti[3];
        for (int rr = 0; rr < 3; rr++)
            ti[rr] = -(D[0 * 3 + rr] * D[9] + D[1 * 3 + rr] * D[10] +
                       D[2 * 3 + rr] * D[11]);
        for (int rr = 0; rr < 3; rr++) {
            float at = P[rr * 3 + 0] * ti[0] + P[rr * 3 + 1] * ti[1] +
                       P[rr * 3 + 2] * ti[2] + P[9 + rr];
            g_A[jj * 12 + rr * 4 + 0] = AR[rr * 3 + 0];
            g_A[jj * 12 + rr * 4 + 1] = AR[rr * 3 + 1];
            g_A[jj * 12 + rr * 4 + 2] = AR[rr * 3 + 2];
            g_A[jj * 12 + rr * 4 + 3] = at;
        }
    }
    if (tid == 0) g_ctr = 0;   // reset for next replay (deterministic)
}

// ---------------------------------------------------------------------------
// Kernel 2: heavy per-point pass, packed f32x2 math, 4 points/thread.
// __launch_bounds__(256,4) caps regs at 64 -> occupancy 50% (was 34%).
// A matrix read from shared as ulonglong2 pairs -> LDS.128 (half the LDS ops).
// ---------------------------------------------------------------------------
__device__ __forceinline__ unsigned long long fma2(unsigned long long a,
                                                   unsigned long long b,
                                                   unsigned long long c) {
    unsigned long long d;
    asm("fma.rn.f32x2 %0, %1, %2, %3;" : "=l"(d) : "l"(a), "l"(b), "l"(c));
    return d;
}

__global__ void __launch_bounds__(256, 4) k_lbs_vec(
    const float* __restrict__ points, const float* __restrict__ weights,
    float* __restrict__ out, int N, long long nGroups) {
    __shared__ __align__(16) unsigned long long sA[NJ * 12];  // {a,a} packed
    for (int i = threadIdx.x; i < NJ * 12; i += blockDim.x) {
        unsigned long long u = (unsigned long long)__float_as_uint(g_A[i]);
        sA[i] = u | (u << 32);
    }
    __syncthreads();

    long long g = (long long)blockIdx.x * blockDim.x + threadIdx.x;
    if (g >= nGroups) return;

    const ulonglong2 X = reinterpret_cast<const ulonglong2*>(points)[g];
    const ulonglong2 Y = reinterpret_cast<const ulonglong2*>(points + (size_t)N)[g];
    const ulonglong2 Z = reinterpret_cast<const ulonglong2*>(points + 2 * (size_t)N)[g];

    unsigned long long vxa = 0ull, vya = 0ull, vza = 0ull;
    unsigned long long vxb = 0ull, vyb = 0ull, vzb = 0ull;

#pragma unroll
    for (int j = 0; j < NJ; j++) {
        const ulonglong2 W =
            reinterpret_cast<const ulonglong2*>(weights + (size_t)j * N)[g];
        const ulonglong2* ap = reinterpret_cast<const ulonglong2*>(&sA[j * 12]);
        const ulonglong2 a01 = ap[0], a23 = ap[1], a45 = ap[2];
        const ulonglong2 a67 = ap[3], a89 = ap[4], aAB = ap[5];
        unsigned long long s;
        // pair a (points 4g, 4g+1)
        s = fma2(a01.x, X.x, a23.y); s = fma2(a01.y, Y.x, s); s = fma2(a23.x, Z.x, s); vxa = fma2(W.x, s, vxa);
        s = fma2(a45.x, X.x, a67.y); s = fma2(a45.y, Y.x, s); s = fma2(a67.x, Z.x, s); vya = fma2(W.x, s, vya);
        s = fma2(a89.x, X.x, aAB.y); s = fma2(a89.y, Y.x, s); s = fma2(aAB.x, Z.x, s); vza = fma2(W.x, s, vza);
        // pair b (points 4g+2, 4g+3)
        s = fma2(a01.x, X.y, a23.y); s = fma2(a01.y, Y.y, s); s = fma2(a23.x, Z.y, s); vxb = fma2(W.y, s, vxb);
        s = fma2(a45.x, X.y, a67.y); s = fma2(a45.y, Y.y, s); s = fma2(a67.x, Z.y, s); vyb = fma2(W.y, s, vyb);
        s = fma2(a89.x, X.y, aAB.y); s = fma2(a89.y, Y.y, s); s = fma2(aAB.x, Z.y, s); vzb = fma2(W.y, s, vzb);
    }

    ulonglong2 o;
    o.x = vxa; o.y = vxb; reinterpret_cast<ulonglong2*>(out)[g] = o;
    o.x = vya; o.y = vyb; reinterpret_cast<ulonglong2*>(out + (size_t)N)[g] = o;
    o.x = vza; o.y = vzb; reinterpret_cast<ulonglong2*>(out + 2 * (size_t)N)[g] = o;
}

// Scalar fallback (only used if N % 4 != 0 — not the case for this problem).
__global__ void k_lbs_scalar(const float* __restrict__ points,
                             const float* __restrict__ weights,
                             float* __restrict__ out, int N) {
    __shared__ float sA[NJ * 12];
    for (int i = threadIdx.x; i < NJ * 12; i += blockDim.x) sA[i] = g_A[i];
    __syncthreads();
    long long n = (long long)blockIdx.x * blockDim.x + threadIdx.x;
    if (n >= N) return;
    float px = points[n], py = points[(size_t)N + n], pz = points[2 * (size_t)N + n];
    float vx = 0.f, vy = 0.f, vz = 0.f;
#pragma unroll
    for (int j = 0; j < NJ; j++) {
        float w = weights[(size_t)j * N + n];
        const float* a = &sA[j * 12];
        vx += w * (a[0] * px + a[1] * py + a[2]  * pz + a[3]);
        vy += w * (a[4] * px + a[5] * py + a[6]  * pz + a[7]);
        vz += w * (a[8] * px + a[9] * py + a[10] * pz + a[11]);
    }
    out[n] = vx; out[(size_t)N + n] = vy; out[2 * (size_t)N + n] = vz;
}

// ---------------------------------------------------------------------------
extern "C" void kernel_launch(void* const* d_in, const int* in_sizes, int n_in,
                              void* d_out, int out_size) {
    const float* points      = (const float*)d_in[0];
    const float* weights     = (const float*)d_in[1];
    const float* beta        = (const float*)d_in[2];
    const float* theta       = (const float*)d_in[3];
    const float* da_theta    = (const float*)d_in[4];
    const float* shapedirs   = (const float*)d_in[5];
    const float* v_template  = (const float*)d_in[6];
    const float* J_regressor = (const float*)d_in[7];

    int N  = in_sizes[0] / 3;          // number of points
    int NV = in_sizes[5] / 30;         // template vertex count

    // fused prep: joints + (last block) transforms
    k_prep<<<NJ, 256>>>(J_regressor, v_template, shapedirs, beta,
                        theta, da_theta, NV);

    // main pass
    if ((N & 3) == 0) {
        long long nGroups = (long long)N / 4;
        int blocks = (int)((nGroups + 255) / 256);
        k_lbs_vec<<<blocks, 256>>>(points, weights, (float*)d_out, N, nGroups);
    } else {
        int blocks = (N + 255) / 256;
        k_lbs_scalar<<<blocks, 256>>>(points, weights, (float*)d_out, N);
    }
}